// round 8
// baseline (speedup 1.0000x reference)
#include <cuda_runtime.h>
#include <math.h>
#include <stdint.h>

// Problem constants (Gemma attention, B=2,S=2048,HID=2048,H=8,KH=1,D=256)
#define BB   2
#define SS   2048
#define HID_ 2048
#define HH   8
#define DD   256
#define NQKV 2560   // packed Q(2048) + K(256) + V(256)

typedef long long ll;

// ---------------------------------------------------------------------------
// Scratch (__device__ globals — allocation-free)
// ---------------------------------------------------------------------------
__device__ float g_qkv[(size_t)BB * SS * NQKV];      // fp32 qkv proj
__device__ float g_bqkv[NQKV];
__device__ float g_vT[(size_t)BB * DD * SS];         // fp32 vT
__device__ float g_ctx[(size_t)BB * SS * HH * DD];   // fp32 ctx

__device__ int8_t g_h1[(size_t)BB * SS * HID_],  g_h2[(size_t)BB * SS * HID_];
__device__ int8_t g_w1[(size_t)NQKV * HID_],     g_w2[(size_t)NQKV * HID_];
__device__ int8_t g_wo1[(size_t)HID_ * HH * DD], g_wo2[(size_t)HID_ * HH * DD];
__device__ int8_t g_q1[(size_t)BB * SS * HH * DD], g_q2[(size_t)BB * SS * HH * DD];
__device__ int8_t g_k1[(size_t)BB * SS * DD],      g_k2[(size_t)BB * SS * DD];
__device__ int8_t g_vt1[(size_t)BB * DD * SS],     g_vt2[(size_t)BB * DD * SS];
__device__ int8_t g_a1[(size_t)BB * HH * SS * SS];
__device__ int8_t g_a2[(size_t)BB * HH * SS * SS];
__device__ int8_t g_c1[(size_t)BB * SS * HH * DD], g_c2[(size_t)BB * SS * HH * DD];

__device__ float g_sh[BB * SS];
__device__ float g_sw[NQKV];
__device__ float g_swo[HID_];
__device__ float g_sq[BB * SS * HH];
__device__ float g_sk[BB * SS];
__device__ float g_svt[BB * DD];
__device__ float g_sa[BB * HH * SS];
__device__ float g_sc[BB * SS];

// ---------------------------------------------------------------------------
// PTX helpers (sm_80-era: cp.async / ldmatrix / mma.sync — valid on sm_103)
// ---------------------------------------------------------------------------
__device__ __forceinline__ uint32_t smem_u32(const void* p) {
    uint32_t a;
    asm("{ .reg .u64 t; cvta.to.shared.u64 t, %1; cvt.u32.u64 %0, t; }"
        : "=r"(a) : "l"(p));
    return a;
}
__device__ __forceinline__ void cp16(uint32_t dst, const void* src) {
    asm volatile("cp.async.cg.shared.global [%0], [%1], 16;"
                 :: "r"(dst), "l"(src) : "memory");
}
#define CP_COMMIT() asm volatile("cp.async.commit_group;" ::: "memory")
#define CP_WAIT(n)  asm volatile("cp.async.wait_group %0;" :: "n"(n) : "memory")

__device__ __forceinline__ void ldm_x4(uint32_t* r, uint32_t addr) {
    asm volatile("ldmatrix.sync.aligned.m8n8.x4.shared.b16 {%0,%1,%2,%3}, [%4];"
                 : "=r"(r[0]), "=r"(r[1]), "=r"(r[2]), "=r"(r[3]) : "r"(addr));
}
__device__ __forceinline__ void imma(int* c, const uint32_t* a,
                                     uint32_t b0, uint32_t b1) {
    asm volatile(
        "mma.sync.aligned.m16n8k32.row.col.s32.s8.s8.s32 "
        "{%0,%1,%2,%3}, {%4,%5,%6,%7}, {%8,%9}, {%0,%1,%2,%3};"
        : "+r"(c[0]), "+r"(c[1]), "+r"(c[2]), "+r"(c[3])
        : "r"(a[0]), "r"(a[1]), "r"(a[2]), "r"(a[3]), "r"(b0), "r"(b1));
}

__device__ __forceinline__ void quant2(float a, int8_t& o1, int8_t& o2) {
    int a1 = __float2int_rn(a);
    a1 = max(-127, min(127, a1));
    int a2 = __float2int_rn((a - (float)a1) * 256.0f);
    a2 = max(-127, min(127, a2));
    o1 = (int8_t)a1;
    o2 = (int8_t)a2;
}

// ===========================================================================
// 2-slice int8 NT GEMM:  C = alpha * sA_r * sB_c * (A @ B^T) + bias
//   Tile 128x128x64, 512 threads (16 warps, warp 32x32), 4-stage cp.async.
//   All dims multiples of (128,128,64).
// ===========================================================================
#define ROWB   80                  // 64 int8 + 16B pad
#define ATB    (128 * ROWB)        // 10240 per tile
#define OFF_A2 ATB
#define OFF_B1 (2 * ATB)
#define OFF_B2 (3 * ATB)
#define STAGE_B (4 * ATB)          // 40960
#define NSTAGE 4
#define IGEMM_SMEM (NSTAGE * STAGE_B)  // 163840

__global__ __launch_bounds__(512, 1)
void igemm_nt(const int8_t* __restrict__ A1, const int8_t* __restrict__ A2,
              const int8_t* __restrict__ B1, const int8_t* __restrict__ B2,
              const float* __restrict__ sA, const float* __restrict__ sB,
              const float* __restrict__ bias, float* __restrict__ C,
              int K, int lda, int ldb, int ldc, int Hdim,
              ll sAb, ll sAh, ll sBb, ll sBh, ll sCb, ll sCh,
              ll sab, ll sah, ll sar, ll sbb, ll sbh, ll sbr,
              float alpha)
{
    extern __shared__ __align__(128) char smem[];
    const uint32_t sb = smem_u32(smem);

    const int tid  = threadIdx.x;
    const int wid  = tid >> 5;
    const int lane = tid & 31;
    const int wm   = wid >> 2;          // 0..3  (32-row band)
    const int wn   = wid & 3;           // 0..3  (32-col band)

    {
        int z  = blockIdx.z;
        int bz = z / Hdim;
        int hz = z - bz * Hdim;
        ll oA = (ll)bz * sAb + (ll)hz * sAh + (ll)blockIdx.y * 128 * lda;
        ll oB = (ll)bz * sBb + (ll)hz * sBh + (ll)blockIdx.x * 128 * ldb;
        ll oC = (ll)bz * sCb + (ll)hz * sCh
              + (ll)blockIdx.y * 128 * ldc + (ll)blockIdx.x * 128;
        A1 += oA; A2 += oA; B1 += oB; B2 += oB; C += oC;
        sA += (ll)bz * sab + (ll)hz * sah + (ll)blockIdx.y * 128 * sar;
        sB += (ll)bz * sbb + (ll)hz * sbh + (ll)blockIdx.x * 128 * sbr;
    }

    const int nc = K >> 6;

    // cp.async mapping: each tile 128 rows x 64B -> one 16B chunk per thread
    const int  crow = tid >> 2;
    const int  ccol = (tid & 3) * 16;
    const int8_t* gA1 = A1 + (ll)crow * lda + ccol;
    const int8_t* gA2 = A2 + (ll)crow * lda + ccol;
    const int8_t* gB1 = B1 + (ll)crow * ldb + ccol;
    const int8_t* gB2 = B2 + (ll)crow * ldb + ccol;
    const uint32_t dst = sb + crow * ROWB + ccol;

    auto issue = [&](int stage, int c) {
        if (c < nc) {
            const int k0 = c << 6;
            const uint32_t so = stage * STAGE_B;
            cp16(dst + so,          gA1 + k0);
            cp16(dst + so + OFF_A2, gA2 + k0);
            cp16(dst + so + OFF_B1, gB1 + k0);
            cp16(dst + so + OFF_B2, gB2 + k0);
        }
        CP_COMMIT();
    };

    int accM[2][4][4], accX[2][4][4];
#pragma unroll
    for (int i = 0; i < 2; i++)
#pragma unroll
        for (int j = 0; j < 4; j++)
#pragma unroll
            for (int r = 0; r < 4; r++) { accM[i][j][r] = 0; accX[i][j][r] = 0; }

    issue(0, 0);
    issue(1, 1);
    issue(2, 2);

    // ldmatrix lane addressing: rows 0..15 at byte 0, rows 0..15 at byte 16
    const uint32_t loff = (uint32_t)(lane & 15) * ROWB + ((lane >> 4) << 4);

    for (int c = 0; c < nc; c++) {
        CP_WAIT(2);
        __syncthreads();
        issue((c + 3) & (NSTAGE - 1), c + 3);

        const uint32_t st    = sb + (c & (NSTAGE - 1)) * STAGE_B;
        const uint32_t aBase = st + (wm * 32) * ROWB + loff;
        const uint32_t bBase = st + OFF_B1 + (wn * 32) * ROWB + loff;

        uint32_t b_[2][2][4];   // [slice][ks][reg]
#pragma unroll
        for (int s = 0; s < 2; s++)
#pragma unroll
            for (int ks = 0; ks < 2; ks++)
                ldm_x4(b_[s][ks], bBase + s * ATB + ks * 32);

#pragma unroll
        for (int mt = 0; mt < 2; mt++) {
            uint32_t a_[2][2][4];
#pragma unroll
            for (int s = 0; s < 2; s++)
#pragma unroll
                for (int ks = 0; ks < 2; ks++)
                    ldm_x4(a_[s][ks], aBase + s * ATB + mt * (16 * ROWB) + ks * 32);

#pragma unroll
            for (int j = 0; j < 4; j++) {
                const int jj = j & 1;          // 8-col group within 16
                const int jg = j >> 1;         // which 16-col half
                int t2[4] = {0, 0, 0, 0};
#pragma unroll
                for (int ks = 0; ks < 2; ks++) {
                    // NOTE: b regs for n-group: matrices (jj + jg*?) — B tile is
                    // 32 n-rows per warp: group j covers n = j*8..j*8+7.
                    // ldmatrix over 16-row window starting at wn*32: we load two
                    // 16-row windows? No: bBase covers rows wn*32..wn*32+15 only.
                    // So handle j<2 from this window; j>=2 needs +16 rows.
                    (void)jg;
                }
                (void)jj; (void)t2;
            }
        }
        // ---- actual MMA block (restructured below for clarity) ----
#pragma unroll
        for (int half = 0; half < 2; half++) {          // n rows wn*32+half*16
            uint32_t bh[2][2][4];                       // [slice][ks][reg]
#pragma unroll
            for (int s = 0; s < 2; s++)
#pragma unroll
                for (int ks = 0; ks < 2; ks++) {
                    if (half == 0) {
                        bh[s][ks][0] = b_[s][ks][0]; bh[s][ks][1] = b_[s][ks][1];
                        bh[s][ks][2] = b_[s][ks][2]; bh[s][ks][3] = b_[s][ks][3];
                    } else {
                        ldm_x4(bh[s][ks],
                               bBase + s * ATB + 16 * ROWB + ks * 32);
                    }
                }
#pragma unroll
            for (int mt = 0; mt < 2; mt++) {
                uint32_t a_[2][2][4];
#pragma unroll
                for (int s = 0; s < 2; s++)
#pragma unroll
                    for (int ks = 0; ks < 2; ks++)
                        ldm_x4(a_[s][ks],
                               aBase + s * ATB + mt * (16 * ROWB) + ks * 32);
#pragma unroll
                for (int jj = 0; jj < 2; jj++) {
                    const int j = half * 2 + jj;
                    int t2[4] = {0, 0, 0, 0};
#pragma unroll
                    for (int ks = 0; ks < 2; ks++) {
                        imma(accM[mt][j], a_[0][ks], bh[0][ks][jj], bh[0][ks][2 + jj]);
                        imma(accX[mt][j], a_[0][ks], bh[1][ks][jj], bh[1][ks][2 + jj]);
                        imma(accX[mt][j], a_[1][ks], bh[0][ks][jj], bh[0][ks][2 + jj]);
                        imma(t2,          a_[1][ks], bh[1][ks][jj], bh[1][ks][2 + jj]);
                    }
#pragma unroll
                    for (int r = 0; r < 4; r++)
                        accX[mt][j][r] += (t2[r] + 128) >> 8;
                }
            }
        }
    }

    // ---- epilogue:  C = alpha*sA*sB*(accM + accX*2^-8) + bias ----
    const int colblk = blockIdx.x << 7;
#pragma unroll
    for (int mt = 0; mt < 2; mt++) {
        const int row0 = wm * 32 + mt * 16 + (lane >> 2);
#pragma unroll
        for (int hrow = 0; hrow < 2; hrow++) {
            const int row = row0 + hrow * 8;
            const float fa = alpha * sA[(ll)row * sar];
#pragma unroll
            for (int j = 0; j < 4; j++) {
                const int col = wn * 32 + j * 8 + (lane & 3) * 2;
                float v0 = (float)accM[mt][j][hrow * 2 + 0]
                         + 0x1p-8f * (float)accX[mt][j][hrow * 2 + 0];
                float v1 = (float)accM[mt][j][hrow * 2 + 1]
                         + 0x1p-8f * (float)accX[mt][j][hrow * 2 + 1];
                v0 *= fa * sB[(ll)col * sbr];
                v1 *= fa * sB[(ll)(col + 1) * sbr];
                if (bias) { v0 += bias[colblk + col]; v1 += bias[colblk + col + 1]; }
                *(float2*)(C + (ll)row * ldc + col) = make_float2(v0, v1);
            }
        }
    }
}

// ---------------------------------------------------------------------------
// Row quantizer: fp32 row (length C, stride ldx) -> 2x int8 slices + scale
// ---------------------------------------------------------------------------
__global__ __launch_bounds__(256)
void rowquant(const float* __restrict__ x, int ldx, int C,
              int8_t* __restrict__ q1, int8_t* __restrict__ q2,
              float* __restrict__ sc)
{
    const int row = blockIdx.x;
    x += (ll)row * ldx;
    const int tid  = threadIdx.x;
    const int w    = tid >> 5;
    const int lane = tid & 31;
    __shared__ float red[8];

    float m = 0.f;
    for (int i = tid; i < C; i += 256) m = fmaxf(m, fabsf(x[i]));
#pragma unroll
    for (int o = 16; o; o >>= 1) m = fmaxf(m, __shfl_xor_sync(0xffffffffu, m, o));
    if (lane == 0) red[w] = m;
    __syncthreads();
#pragma unroll
    for (int i = 0; i < 8; i++) m = fmaxf(m, red[i]);
    m = fmaxf(m, 1e-30f);
    const float inv = 127.0f / m;
    if (tid == 0) sc[row] = m * (1.0f / 127.0f);

    for (int i = tid; i < C; i += 256) {
        int8_t o1, o2;
        quant2(x[i] * inv, o1, o2);
        q1[(ll)row * C + i] = o1;
        q2[(ll)row * C + i] = o2;
    }
}

// ---------------------------------------------------------------------------
// RoPE + quantize: one block (128 thr) per (bs, h) row of 256 elems.
// ---------------------------------------------------------------------------
__global__ __launch_bounds__(128)
void rope_quant(const float* __restrict__ src, const int* __restrict__ pos,
                int8_t* __restrict__ q1, int8_t* __restrict__ q2,
                float* __restrict__ sc, int Hx)
{
    const int blk = blockIdx.x;
    const int hh  = blk % Hx;
    const int bs  = blk / Hx;
    const int t   = threadIdx.x;           // 0..127
    const int w   = t >> 5, lane = t & 31;
    __shared__ float red[4];

    const float p   = (float)pos[bs];
    const float ivf = __expf(-(float)t * (9.210340371976184f / 128.f));
    float sn, cs;
    sincosf(p * ivf, &sn, &cs);
    const float* xr = src + (ll)bs * NQKV + hh * DD;
    const float x1 = xr[t], x2 = xr[t + 128];
    const float y1 = cs * x1 - sn * x2;
    const float y2 = sn * x1 + cs * x2;

    float m = fmaxf(fabsf(y1), fabsf(y2));
#pragma unroll
    for (int o = 16; o; o >>= 1) m = fmaxf(m, __shfl_xor_sync(0xffffffffu, m, o));
    if (lane == 0) red[w] = m;
    __syncthreads();
#pragma unroll
    for (int i = 0; i < 4; i++) m = fmaxf(m, red[i]);
    m = fmaxf(m, 1e-30f);
    const float inv = 127.0f / m;
    if (t == 0) sc[blk] = m * (1.0f / 127.0f);

    const ll ob = (ll)blk * DD;
    int8_t o1, o2;
    quant2(y1 * inv, o1, o2); q1[ob + t] = o1;        q2[ob + t] = o2;
    quant2(y2 * inv, o1, o2); q1[ob + 128 + t] = o1;  q2[ob + 128 + t] = o2;
}

// ---------------------------------------------------------------------------
// Transpose v from packed qkv (col 2304) fp32 -> vT (b,D,S) fp32
// ---------------------------------------------------------------------------
__global__ void transpose_v(const float* __restrict__ qkv, float* __restrict__ vT)
{
    __shared__ float t[32][33];
    int b  = blockIdx.z;
    int s0 = blockIdx.x * 32;
    int d0 = blockIdx.y * 32;
    int tx = threadIdx.x, ty = threadIdx.y;
    const float* src = qkv + (ll)b * SS * NQKV + 2304;
#pragma unroll
    for (int i = 0; i < 32; i += 8)
        t[ty + i][tx] = src[(ll)(s0 + ty + i) * NQKV + d0 + tx];
    __syncthreads();
    float* dst = vT + (ll)b * DD * SS;
#pragma unroll
    for (int i = 0; i < 32; i += 8)
        dst[(ll)(d0 + ty + i) * SS + s0 + tx] = t[tx][ty + i];
}

// ---------------------------------------------------------------------------
// Row softmax over attn (B,H,S,S) in place (+mask) + int8 quantized output.
// Row max of probs is exactly 1/sumexp -> scale is free.
// ---------------------------------------------------------------------------
__global__ __launch_bounds__(256)
void softmax_quant(float* __restrict__ attn, const float* __restrict__ mask,
                   int8_t* __restrict__ q1, int8_t* __restrict__ q2,
                   float* __restrict__ sc)
{
    const int HSrows = HH * SS;
    ll r = blockIdx.x;
    int b = (int)(r / HSrows);
    float* row = attn + r * (ll)SS;
    const float* mrow = mask + (ll)b * SS;

    int tid  = threadIdx.x;
    int w    = tid >> 5;
    int lane = tid & 31;
    __shared__ float red[8];

    float v[8];
    float mx = -1e30f;
#pragma unroll
    for (int i = 0; i < 8; i++) {
        int c = tid + i * 256;
        float x = row[c] + mrow[c];
        v[i] = x;
        mx = fmaxf(mx, x);
    }
#pragma unroll
    for (int o = 16; o; o >>= 1) mx = fmaxf(mx, __shfl_xor_sync(0xffffffffu, mx, o));
    if (lane == 0) red[w] = mx;
    __syncthreads();
#pragma unroll
    for (int i = 0; i < 8; i++) mx = fmaxf(mx, red[i]);

    float s = 0.f;
#pragma unroll
    for (int i = 0; i < 8; i++) {
        v[i] = __expf(v[i] - mx);
        s += v[i];
    }
#pragma unroll
    for (int o = 16; o; o >>= 1) s += __shfl_xor_sync(0xffffffffu, s, o);
    __syncthreads();
    if (lane == 0) red[w] = s;
    __syncthreads();
    s = 0.f;
#pragma unroll
    for (int i = 0; i < 8; i++) s += red[i];
    const float inv = 1.f / s;
    if (tid == 0) sc[r] = inv * (1.0f / 127.0f);

    const ll rb = r * (ll)SS;
#pragma unroll
    for (int i = 0; i < 8; i++) {
        const int c = tid + i * 256;
        row[c] = v[i] * inv;
        int8_t o1, o2;
        quant2(127.0f * v[i], o1, o2);
        q1[rb + c] = o1;
        q2[rb + c] = o2;
    }
}

// ---------------------------------------------------------------------------
// Launch
// ---------------------------------------------------------------------------
extern "C" void kernel_launch(void* const* d_in, const int* in_sizes, int n_in,
                              void* d_out, int out_size)
{
    (void)in_sizes; (void)n_in; (void)out_size;

    const float* hidden = (const float*)d_in[0];
    const float* mask   = (const float*)d_in[1];
    const int*   pos    = (const int*)  d_in[2];
    const float* Wq     = (const float*)d_in[3];
    const float* bq     = (const float*)d_in[4];
    const float* Wk     = (const float*)d_in[5];
    const float* bk     = (const float*)d_in[6];
    const float* Wv     = (const float*)d_in[7];
    const float* bv     = (const float*)d_in[8];
    const float* Wo     = (const float*)d_in[9];
    const float* bo     = (const float*)d_in[10];

    float* out  = (float*)d_out;                      // (B,S,HID)
    float* attn = out + (size_t)BB * SS * HID_;       // (B,H,S,S)

    float *qkv, *bqkv, *vT, *ctx;
    int8_t *h1, *h2, *w1, *w2, *wo1, *wo2, *q1, *q2, *k1, *k2;
    int8_t *vt1, *vt2, *a1, *a2, *c1, *c2;
    float *sh, *sw, *swo, *sq, *sk, *svt, *sa, *sc;

    cudaGetSymbolAddress((void**)&qkv,  g_qkv);
    cudaGetSymbolAddress((void**)&bqkv, g_bqkv);
    cudaGetSymbolAddress((void**)&vT,   g_vT);
    cudaGetSymbolAddress((void**)&ctx,  g_ctx);
    cudaGetSymbolAddress((void**)&h1,  g_h1);   cudaGetSymbolAddress((void**)&h2,  g_h2);
    cudaGetSymbolAddress((void**)&w1,  g_w1);   cudaGetSymbolAddress((void**)&w2,  g_w2);
    cudaGetSymbolAddress((void**)&wo1, g_wo1);  cudaGetSymbolAddress((void**)&wo2, g_wo2);
    cudaGetSymbolAddress((void**)&q1,  g_q1);   cudaGetSymbolAddress((void**)&q2,  g_q2);
    cudaGetSymbolAddress((void**)&k1,  g_k1);   cudaGetSymbolAddress((void**)&k2,  g_k2);
    cudaGetSymbolAddress((void**)&vt1, g_vt1);  cudaGetSymbolAddress((void**)&vt2, g_vt2);
    cudaGetSymbolAddress((void**)&a1,  g_a1);   cudaGetSymbolAddress((void**)&a2,  g_a2);
    cudaGetSymbolAddress((void**)&c1,  g_c1);   cudaGetSymbolAddress((void**)&c2,  g_c2);
    cudaGetSymbolAddress((void**)&sh,  g_sh);
    cudaGetSymbolAddress((void**)&sw,  g_sw);
    cudaGetSymbolAddress((void**)&swo, g_swo);
    cudaGetSymbolAddress((void**)&sq,  g_sq);
    cudaGetSymbolAddress((void**)&sk,  g_sk);
    cudaGetSymbolAddress((void**)&svt, g_svt);
    cudaGetSymbolAddress((void**)&sa,  g_sa);
    cudaGetSymbolAddress((void**)&sc,  g_sc);

    cudaFuncSetAttribute(igemm_nt, cudaFuncAttributeMaxDynamicSharedMemorySize,
                         IGEMM_SMEM);

    const int M = BB * SS;   // 4096
    dim3 q256(256);
    dim3 gblk(512);

    // 0) quantize inputs (weights packed into Wqkv row space)
    rowquant<<<M,    q256>>>(hidden, HID_, HID_, h1, h2, sh);
    rowquant<<<2048, q256>>>(Wq, HID_, HID_, w1, w2, sw);
    rowquant<<<256,  q256>>>(Wk, HID_, HID_, w1 + (size_t)2048 * HID_,
                             w2 + (size_t)2048 * HID_, sw + 2048);
    rowquant<<<256,  q256>>>(Wv, HID_, HID_, w1 + (size_t)2304 * HID_,
                             w2 + (size_t)2304 * HID_, sw + 2304);
    rowquant<<<2048, q256>>>(Wo, HID_, HID_, wo1, wo2, swo);
    cudaMemcpyAsync(bqkv,        bq, 2048 * sizeof(float), cudaMemcpyDeviceToDevice);
    cudaMemcpyAsync(bqkv + 2048, bk,  256 * sizeof(float), cudaMemcpyDeviceToDevice);
    cudaMemcpyAsync(bqkv + 2304, bv,  256 * sizeof(float), cudaMemcpyDeviceToDevice);

    // 1) fused QKV projection: qkv = hidden @ Wqkv^T + bqkv  (4096 x 2560 x 2048)
    igemm_nt<<<dim3(NQKV / 128, M / 128, 1), gblk, IGEMM_SMEM>>>(
        h1, h2, w1, w2, sh, sw, bqkv, qkv,
        HID_, HID_, HID_, NQKV, 1,
        0, 0, 0, 0, 0, 0,
        0, 0, 1, 0, 0, 1, 1.0f);

    // 2) RoPE + quantize q, k
    rope_quant<<<BB * SS * HH, 128>>>(qkv,        pos, q1, q2, sq, HH);
    rope_quant<<<BB * SS,      128>>>(qkv + 2048, pos, k1, k2, sk, 1);

    // 3) vT fp32 + quantize rows
    transpose_v<<<dim3(SS / 32, DD / 32, BB), dim3(32, 8)>>>(qkv, vT);
    rowquant<<<BB * DD, q256>>>(vT, SS, SS, vt1, vt2, svt);

    // 4) scores = (q @ k^T)/16 -> attn fp32 (raw)
    igemm_nt<<<dim3(SS / 128, SS / 128, BB * HH), gblk, IGEMM_SMEM>>>(
        q1, q2, k1, k2, sq, sk, nullptr, attn,
        DD, HH * DD, DD, SS, HH,
        (ll)SS * HH * DD, (ll)DD,
        (ll)SS * DD, 0,
        (ll)HH * SS * SS, (ll)SS * SS,
        (ll)SS * HH, 1, HH,
        (ll)SS, 0, 1,
        0.0625f);

    // 5) softmax in place (+mask) + int8 quantized attn
    softmax_quant<<<BB * HH * SS, q256>>>(attn, mask, a1, a2, sa);

    // 6) ctx = attn @ v  (fp32)
    igemm_nt<<<dim3(DD / 128, SS / 128, BB * HH), gblk, IGEMM_SMEM>>>(
        a1, a2, vt1, vt2, sa, svt, nullptr, ctx,
        SS, SS, SS, HH * DD, HH,
        (ll)HH * SS * SS, (ll)SS * SS,
        (ll)DD * SS, 0,
        (ll)SS * HH * DD, (ll)DD,
        (ll)HH * SS, (ll)SS, 1,
        (ll)DD, 0, 1,
        1.0f);

    // 7) quantize ctx rows
    rowquant<<<M, q256>>>(ctx, HH * DD, HH * DD, c1, c2, sc);

    // 8) out = ctx @ Wo^T + bo
    igemm_nt<<<dim3(HID_ / 128, M / 128, 1), gblk, IGEMM_SMEM>>>(
        c1, c2, wo1, wo2, sc, swo, bo, out,
        HH * DD, HH * DD, HH * DD, HID_, 1,
        0, 0, 0, 0, 0, 0,
        0, 0, 1, 0, 0, 1, 1.0f);
}

// round 9
// speedup vs baseline: 2.1932x; 2.1932x over previous
#include <cuda_runtime.h>
#include <cuda_bf16.h>
#include <math.h>
#include <stdint.h>

// Problem constants (Gemma attention, B=2,S=2048,HID=2048,H=8,KH=1,D=256)
#define BB   2
#define SS   2048
#define HID_ 2048
#define HH   8
#define DD   256
#define NQKV 2560   // packed Q(2048) + K(256) + V(256)

typedef __nv_bfloat16 bf16;
typedef __nv_bfloat162 bf162;

// ---------------------------------------------------------------------------
// Scratch (__device__ globals — allocation-free)
// ---------------------------------------------------------------------------
__device__ float g_qkv[(size_t)BB * SS * NQKV];       // 41.9 MB fp32 qkv proj
__device__ float g_bqkv[NQKV];

__device__ bf16 g_hidH[(size_t)BB * SS * HID_], g_hidL[(size_t)BB * SS * HID_];
__device__ bf16 g_WqkvH[(size_t)NQKV * HID_],  g_WqkvL[(size_t)NQKV * HID_];
__device__ bf16 g_WoH[(size_t)HID_ * HH * DD], g_WoL[(size_t)HID_ * HH * DD];
__device__ bf16 g_qH[(size_t)BB * SS * HH * DD], g_qL[(size_t)BB * SS * HH * DD];
__device__ bf16 g_kH[(size_t)BB * SS * DD],      g_kL[(size_t)BB * SS * DD];
__device__ bf16 g_vTH[(size_t)BB * DD * SS],     g_vTL[(size_t)BB * DD * SS];
__device__ bf16 g_attnH[(size_t)BB * HH * SS * SS];   // 134 MB
__device__ bf16 g_attnL[(size_t)BB * HH * SS * SS];   // 134 MB
__device__ bf16 g_ctxH[(size_t)BB * SS * HH * DD],  g_ctxL[(size_t)BB * SS * HH * DD];

// ---------------------------------------------------------------------------
// PTX helpers (sm_80-era: cp.async / ldmatrix / mma.sync — valid on sm_103)
// ---------------------------------------------------------------------------
__device__ __forceinline__ uint32_t smem_u32(const void* p) {
    uint32_t a;
    asm("{ .reg .u64 t; cvta.to.shared.u64 t, %1; cvt.u32.u64 %0, t; }"
        : "=r"(a) : "l"(p));
    return a;
}

__device__ __forceinline__ void cp16(uint32_t dst, const void* src) {
    asm volatile("cp.async.cg.shared.global [%0], [%1], 16;"
                 :: "r"(dst), "l"(src) : "memory");
}
#define CP_COMMIT() asm volatile("cp.async.commit_group;" ::: "memory")
#define CP_WAIT(n)  asm volatile("cp.async.wait_group %0;" :: "n"(n) : "memory")

__device__ __forceinline__ void ldm_x4(uint32_t* r, uint32_t addr) {
    asm volatile("ldmatrix.sync.aligned.m8n8.x4.shared.b16 {%0,%1,%2,%3}, [%4];"
                 : "=r"(r[0]), "=r"(r[1]), "=r"(r[2]), "=r"(r[3]) : "r"(addr));
}

__device__ __forceinline__ void mma_bf16(float* c, const uint32_t* a,
                                         uint32_t b0, uint32_t b1) {
    asm volatile(
        "mma.sync.aligned.m16n8k16.row.col.f32.bf16.bf16.f32 "
        "{%0,%1,%2,%3}, {%4,%5,%6,%7}, {%8,%9}, {%0,%1,%2,%3};"
        : "+f"(c[0]), "+f"(c[1]), "+f"(c[2]), "+f"(c[3])
        : "r"(a[0]), "r"(a[1]), "r"(a[2]), "r"(a[3]), "r"(b0), "r"(b1));
}

__device__ __forceinline__ void split1(float v, bf16& h, bf16& l) {
    h = __float2bfloat16(v);
    l = __float2bfloat16(v - __bfloat162float(h));
}

// ===========================================================================
// Split-bf16 NT GEMM on HMMA:  C = alpha*(Ah·Bh^T + Al·Bh^T + Ah·Bl^T) + bias
//   CTA tile 256x128x32, 256 threads (8 warps, warp tile 64x64), 3-stage
//   cp.async pipeline. All dims multiples of (256,128,32).
// ===========================================================================
#define ROWB    80                  // 32 bf16 (64B) + 16B pad
#define A_T_B   (256 * ROWB)        // 20480
#define B_T_B   (128 * ROWB)        // 10240
#define OFF_AL  A_T_B               // 20480
#define OFF_BH  (2 * A_T_B)         // 40960
#define OFF_BL  (2 * A_T_B + B_T_B) // 51200
#define STAGE_B (2 * A_T_B + 2 * B_T_B)   // 61440
#define NSTAGE  3
#define HGEMM_SMEM (NSTAGE * STAGE_B)     // 184320

__global__ __launch_bounds__(256, 1)
void hgemm_nt(const bf16* __restrict__ Ah, const bf16* __restrict__ Al,
              const bf16* __restrict__ Bh, const bf16* __restrict__ Bl,
              const float* __restrict__ bias,
              float* __restrict__ C, bf16* __restrict__ Ch, bf16* __restrict__ Cl,
              int K, int lda, int ldb, int ldc, int Hdim,
              long long sAb, long long sAh_,
              long long sBb, long long sBh_,
              long long sCb, long long sCh_,
              float alpha)
{
    extern __shared__ __align__(128) char smem[];
    const uint32_t sb = smem_u32(smem);

    const int tid  = threadIdx.x;
    const int wid  = tid >> 5;
    const int lane = tid & 31;
    const int wm   = wid >> 1;          // 0..3  (64-row band)
    const int wn   = wid & 1;           // 0..1  (64-col band)

    // batch decomposition
    {
        int z  = blockIdx.z;
        int bz = z / Hdim;
        int hz = z - bz * Hdim;
        long long oA = (long long)bz * sAb + (long long)hz * sAh_
                     + (long long)blockIdx.y * 256 * lda;
        long long oB = (long long)bz * sBb + (long long)hz * sBh_
                     + (long long)blockIdx.x * 128 * ldb;
        long long oC = (long long)bz * sCb + (long long)hz * sCh_
                     + (long long)blockIdx.y * 256 * ldc + (long long)blockIdx.x * 128;
        Ah += oA; Al += oA; Bh += oB; Bl += oB;
        if (C)  C  += oC;
        if (Ch) { Ch += oC; Cl += oC; }
    }

    const int nc = K >> 5;

    // cp.async mapping (k32 chunk):
    //   A: 256 rows x 64B, 256 thr -> each thread one full row (4x16B)
    //   B: 128 rows x 64B          -> each thread half a row (2x16B)
    const int rowB = tid >> 1;
    const int cB   = (tid & 1) * 32;     // byte offset in row
    const bf16* gAh = Ah + (long long)tid * lda;
    const bf16* gAl = Al + (long long)tid * lda;
    const bf16* gBh = Bh + (long long)rowB * ldb + cB / 2;
    const bf16* gBl = Bl + (long long)rowB * ldb + cB / 2;
    const uint32_t dA = sb + tid * ROWB;
    const uint32_t dB = sb + OFF_BH + rowB * ROWB + cB;

    auto issue = [&](int stage, int c) {
        if (c < nc) {
            const int k0 = c << 5;
            const uint32_t so = stage * STAGE_B;
#pragma unroll
            for (int u = 0; u < 4; u++) {
                cp16(dA + so + u * 16,          gAh + k0 + u * 8);
                cp16(dA + so + OFF_AL + u * 16, gAl + k0 + u * 8);
            }
            cp16(dB + so,              gBh + k0);
            cp16(dB + so + 16,         gBh + k0 + 8);
            cp16(dB + so + B_T_B,      gBl + k0);
            cp16(dB + so + B_T_B + 16, gBl + k0 + 8);
        }
        CP_COMMIT();
    };

    float acc[4][8][4];
#pragma unroll
    for (int i = 0; i < 4; i++)
#pragma unroll
        for (int j = 0; j < 8; j++)
#pragma unroll
            for (int r = 0; r < 4; r++) acc[i][j][r] = 0.f;

    issue(0, 0);
    issue(1, 1);

    // ldmatrix lane address component: row lane&15, col half at +16B
    const uint32_t loff = (uint32_t)(lane & 15) * ROWB + ((lane >> 4) << 4);

    for (int c = 0; c < nc; c++) {
        CP_WAIT(1);
        __syncthreads();
        issue((c + 2) % NSTAGE, c + 2);

        const uint32_t st    = sb + (c % NSTAGE) * STAGE_B;
        const uint32_t aBase = st + (wm * 64) * ROWB + loff;
        const uint32_t bBase = st + OFF_BH + (wn * 64) * ROWB + loff;

#pragma unroll
        for (int k16 = 0; k16 < 2; k16++) {
            const uint32_t kb = k16 * 32;
            uint32_t bH[4][4], bL[4][4];
#pragma unroll
            for (int nt = 0; nt < 4; nt++) {
                ldm_x4(bH[nt], bBase + nt * (16 * ROWB) + kb);
                ldm_x4(bL[nt], bBase + B_T_B + nt * (16 * ROWB) + kb);
            }
#pragma unroll
            for (int mt = 0; mt < 4; mt++) {
                uint32_t aH[4], aL[4];
                ldm_x4(aH, aBase + mt * (16 * ROWB) + kb);
                ldm_x4(aL, aBase + OFF_AL + mt * (16 * ROWB) + kb);
#pragma unroll
                for (int j = 0; j < 8; j++)
                    mma_bf16(acc[mt][j], aH, bH[j >> 1][j & 1], bH[j >> 1][2 + (j & 1)]);
#pragma unroll
                for (int j = 0; j < 8; j++)
                    mma_bf16(acc[mt][j], aL, bH[j >> 1][j & 1], bH[j >> 1][2 + (j & 1)]);
#pragma unroll
                for (int j = 0; j < 8; j++)
                    mma_bf16(acc[mt][j], aH, bL[j >> 1][j & 1], bL[j >> 1][2 + (j & 1)]);
            }
        }
    }

    // ---- epilogue ----
    const int colblk = blockIdx.x << 7;
#pragma unroll
    for (int mt = 0; mt < 4; mt++) {
        const int row0 = wm * 64 + mt * 16 + (lane >> 2);
#pragma unroll
        for (int hrow = 0; hrow < 2; hrow++) {
            const int row = row0 + hrow * 8;
#pragma unroll
            for (int j = 0; j < 8; j++) {
                const int col = wn * 64 + j * 8 + (lane & 3) * 2;
                float b0 = 0.f, b1 = 0.f;
                if (bias) { b0 = bias[colblk + col]; b1 = bias[colblk + col + 1]; }
                float v0 = acc[mt][j][hrow * 2 + 0] * alpha + b0;
                float v1 = acc[mt][j][hrow * 2 + 1] * alpha + b1;
                const long long ci = (long long)row * ldc + col;
                if (C) *(float2*)(C + ci) = make_float2(v0, v1);
                if (Ch) {
                    bf16 h0, l0, h1, l1;
                    split1(v0, h0, l0);
                    split1(v1, h1, l1);
                    *(bf162*)(Ch + ci) = __halves2bfloat162(h0, h1);
                    *(bf162*)(Cl + ci) = __halves2bfloat162(l0, l1);
                }
            }
        }
    }
}

// ---------------------------------------------------------------------------
// Elementwise fp32 -> (hi,lo) bf16 split
// ---------------------------------------------------------------------------
__global__ void split_arr(const float* __restrict__ s, bf16* __restrict__ h,
                          bf16* __restrict__ l, long long n)
{
    long long i = ((long long)blockIdx.x * blockDim.x + threadIdx.x) * 4;
    if (i >= n) return;
    float4 v = *(const float4*)(s + i);
    bf16 h0, l0, h1, l1, h2, l2, h3, l3;
    split1(v.x, h0, l0); split1(v.y, h1, l1);
    split1(v.z, h2, l2); split1(v.w, h3, l3);
    *(bf162*)(h + i)     = __halves2bfloat162(h0, h1);
    *(bf162*)(h + i + 2) = __halves2bfloat162(h2, h3);
    *(bf162*)(l + i)     = __halves2bfloat162(l0, l1);
    *(bf162*)(l + i + 2) = __halves2bfloat162(l2, l3);
}

// ---------------------------------------------------------------------------
// RoPE + split from packed qkv
// ---------------------------------------------------------------------------
__global__ void rope_split(const float* __restrict__ x, const int* __restrict__ pos,
                           bf16* __restrict__ xh, bf16* __restrict__ xl,
                           int Hx, int total)
{
    int idx = blockIdx.x * blockDim.x + threadIdx.x;
    if (idx >= total) return;
    int j    = idx & 127;
    int rest = idx >> 7;
    int hh   = rest % Hx;
    int bs   = rest / Hx;
    float p  = (float)pos[bs];
    float inv = __expf(-(float)j * (9.210340371976184f / 128.f));
    float f = p * inv;
    float sn, cs;
    sincosf(f, &sn, &cs);
    long long ioff = (long long)bs * NQKV + hh * DD;
    float x1 = x[ioff + j];
    float x2 = x[ioff + 128 + j];
    float y1 = cs * x1 - sn * x2;
    float y2 = sn * x1 + cs * x2;
    long long ooff = ((long long)bs * Hx + hh) * DD;
    bf16 h, l;
    split1(y1, h, l); xh[ooff + j] = h;        xl[ooff + j] = l;
    split1(y2, h, l); xh[ooff + 128 + j] = h;  xl[ooff + 128 + j] = l;
}

// ---------------------------------------------------------------------------
// Transpose v from packed qkv (col 2304) fp32 -> vT (b,D,S) split bf16
// ---------------------------------------------------------------------------
__global__ void transpose_split(const float* __restrict__ qkv,
                                bf16* __restrict__ vTh, bf16* __restrict__ vTl)
{
    __shared__ float t[32][33];
    int b  = blockIdx.z;
    int s0 = blockIdx.x * 32;
    int d0 = blockIdx.y * 32;
    int tx = threadIdx.x, ty = threadIdx.y;
    const float* src = qkv + (long long)b * SS * NQKV + 2304;
#pragma unroll
    for (int i = 0; i < 32; i += 8)
        t[ty + i][tx] = src[(long long)(s0 + ty + i) * NQKV + d0 + tx];
    __syncthreads();
    long long obase = (long long)b * DD * SS;
#pragma unroll
    for (int i = 0; i < 32; i += 8) {
        long long oi = obase + (long long)(d0 + ty + i) * SS + s0 + tx;
        bf16 h, l;
        split1(t[tx][ty + i], h, l);
        vTh[oi] = h;
        vTl[oi] = l;
    }
}

// ---------------------------------------------------------------------------
// Row softmax over attn (B,H,S,S) in place (+mask), also emits split bf16
// ---------------------------------------------------------------------------
__global__ __launch_bounds__(256)
void softmax_split(float* __restrict__ attn, const float* __restrict__ mask,
                   bf16* __restrict__ ah, bf16* __restrict__ al)
{
    const int HSrows = HH * SS;
    long long r = blockIdx.x;
    int b = (int)(r / HSrows);
    float* row = attn + r * (long long)SS;
    const float* mrow = mask + (long long)b * SS;

    int tid  = threadIdx.x;
    int w    = tid >> 5;
    int lane = tid & 31;
    __shared__ float red[8];

    float v[8];
    float mx = -1e30f;
#pragma unroll
    for (int i = 0; i < 8; i++) {
        int c = tid + i * 256;
        float x = row[c] + mrow[c];
        v[i] = x;
        mx = fmaxf(mx, x);
    }
#pragma unroll
    for (int o = 16; o; o >>= 1) mx = fmaxf(mx, __shfl_xor_sync(0xffffffffu, mx, o));
    if (lane == 0) red[w] = mx;
    __syncthreads();
#pragma unroll
    for (int i = 0; i < 8; i++) mx = fmaxf(mx, red[i]);

    float s = 0.f;
#pragma unroll
    for (int i = 0; i < 8; i++) {
        v[i] = __expf(v[i] - mx);
        s += v[i];
    }
#pragma unroll
    for (int o = 16; o; o >>= 1) s += __shfl_xor_sync(0xffffffffu, s, o);
    __syncthreads();
    if (lane == 0) red[w] = s;
    __syncthreads();
    s = 0.f;
#pragma unroll
    for (int i = 0; i < 8; i++) s += red[i];
    float inv = 1.f / s;

    long long rb = r * (long long)SS;
#pragma unroll
    for (int i = 0; i < 8; i++) {
        int c = tid + i * 256;
        float p = v[i] * inv;
        row[c] = p;
        bf16 h, l;
        split1(p, h, l);
        ah[rb + c] = h;
        al[rb + c] = l;
    }
}

// ---------------------------------------------------------------------------
// Launch
// ---------------------------------------------------------------------------
extern "C" void kernel_launch(void* const* d_in, const int* in_sizes, int n_in,
                              void* d_out, int out_size)
{
    (void)in_sizes; (void)n_in; (void)out_size;

    const float* hidden = (const float*)d_in[0];
    const float* mask   = (const float*)d_in[1];
    const int*   pos    = (const int*)  d_in[2];
    const float* Wq     = (const float*)d_in[3];
    const float* bq     = (const float*)d_in[4];
    const float* Wk     = (const float*)d_in[5];
    const float* bk     = (const float*)d_in[6];
    const float* Wv     = (const float*)d_in[7];
    const float* bv     = (const float*)d_in[8];
    const float* Wo     = (const float*)d_in[9];
    const float* bo     = (const float*)d_in[10];

    float* out  = (float*)d_out;                      // (B,S,HID)
    float* attn = out + (size_t)BB * SS * HID_;       // (B,H,S,S)

    float *qkv, *bqkv;
    bf16 *hidH, *hidL, *WqkvH, *WqkvL, *WoH, *WoL;
    bf16 *qH, *qL, *kH, *kL, *vTH, *vTL, *attnH, *attnL, *ctxH, *ctxL;
    cudaGetSymbolAddress((void**)&qkv, g_qkv);
    cudaGetSymbolAddress((void**)&bqkv, g_bqkv);
    cudaGetSymbolAddress((void**)&hidH, g_hidH);   cudaGetSymbolAddress((void**)&hidL, g_hidL);
    cudaGetSymbolAddress((void**)&WqkvH, g_WqkvH); cudaGetSymbolAddress((void**)&WqkvL, g_WqkvL);
    cudaGetSymbolAddress((void**)&WoH, g_WoH);     cudaGetSymbolAddress((void**)&WoL, g_WoL);
    cudaGetSymbolAddress((void**)&qH, g_qH);       cudaGetSymbolAddress((void**)&qL, g_qL);
    cudaGetSymbolAddress((void**)&kH, g_kH);       cudaGetSymbolAddress((void**)&kL, g_kL);
    cudaGetSymbolAddress((void**)&vTH, g_vTH);     cudaGetSymbolAddress((void**)&vTL, g_vTL);
    cudaGetSymbolAddress((void**)&attnH, g_attnH); cudaGetSymbolAddress((void**)&attnL, g_attnL);
    cudaGetSymbolAddress((void**)&ctxH, g_ctxH);   cudaGetSymbolAddress((void**)&ctxL, g_ctxL);

    cudaFuncSetAttribute(hgemm_nt, cudaFuncAttributeMaxDynamicSharedMemorySize,
                         HGEMM_SMEM);

    const int M = BB * SS;   // 4096
    dim3 blk(256);

    // 0) split inputs + pack Wqkv/bias
    {
        long long n;
        n = (long long)BB * SS * HID_;
        split_arr<<<(unsigned)((n / 4 + 255) / 256), blk>>>(hidden, hidH, hidL, n);
        n = (long long)HID_ * HID_;   // Wq rows 0..2047
        split_arr<<<(unsigned)((n / 4 + 255) / 256), blk>>>(Wq, WqkvH, WqkvL, n);
        n = (long long)DD * HID_;     // Wk rows 2048..2303
        split_arr<<<(unsigned)((n / 4 + 255) / 256), blk>>>(
            Wk, WqkvH + (size_t)2048 * HID_, WqkvL + (size_t)2048 * HID_, n);
        // Wv rows 2304..2559
        split_arr<<<(unsigned)((n / 4 + 255) / 256), blk>>>(
            Wv, WqkvH + (size_t)2304 * HID_, WqkvL + (size_t)2304 * HID_, n);
        n = (long long)HID_ * HH * DD;
        split_arr<<<(unsigned)((n / 4 + 255) / 256), blk>>>(Wo, WoH, WoL, n);

        cudaMemcpyAsync(bqkv,        bq, 2048 * sizeof(float), cudaMemcpyDeviceToDevice);
        cudaMemcpyAsync(bqkv + 2048, bk,  256 * sizeof(float), cudaMemcpyDeviceToDevice);
        cudaMemcpyAsync(bqkv + 2304, bv,  256 * sizeof(float), cudaMemcpyDeviceToDevice);
    }

    // 1) fused QKV projection: qkv = hidden @ Wqkv^T + bqkv   (4096 x 2560 x 2048)
    hgemm_nt<<<dim3(NQKV / 128, M / 256, 1), blk, HGEMM_SMEM>>>(
        hidH, hidL, WqkvH, WqkvL, bqkv, qkv, nullptr, nullptr,
        HID_, HID_, HID_, NQKV, 1, 0, 0, 0, 0, 0, 0, 1.0f);

    // 2) RoPE + split q (cols 0..2047) and k (cols 2048..2303)
    {
        int totq = BB * SS * HH * (DD / 2);
        rope_split<<<(totq + 255) / 256, blk>>>(qkv, pos, qH, qL, HH, totq);
        int totk = BB * SS * (DD / 2);
        rope_split<<<(totk + 255) / 256, blk>>>(qkv + 2048, pos, kH, kL, 1, totk);
    }

    // 3) vT split (b,D,S) from qkv cols 2304..2559
    transpose_split<<<dim3(SS / 32, DD / 32, BB), dim3(32, 8)>>>(qkv, vTH, vTL);

    // 4) scores = (q @ k^T)/16 -> attn fp32 region
    hgemm_nt<<<dim3(SS / 128, SS / 256, BB * HH), blk, HGEMM_SMEM>>>(
        qH, qL, kH, kL, nullptr, attn, nullptr, nullptr,
        DD, HH * DD, DD, SS, HH,
        (long long)SS * HH * DD, (long long)DD,
        (long long)SS * DD, 0,
        (long long)HH * SS * SS, (long long)SS * SS,
        0.0625f);

    // 5) softmax in place + split output
    softmax_split<<<BB * HH * SS, blk>>>(attn, mask, attnH, attnL);

    // 6) ctx = attn @ v  -> split bf16 directly
    hgemm_nt<<<dim3(DD / 128, SS / 256, BB * HH), blk, HGEMM_SMEM>>>(
        attnH, attnL, vTH, vTL, nullptr, nullptr, ctxH, ctxL,
        SS, SS, SS, HH * DD, HH,
        (long long)HH * SS * SS, (long long)SS * SS,
        (long long)DD * SS, 0,
        (long long)SS * HH * DD, (long long)DD,
        1.0f);

    // 7) out = ctx @ Wo^T + bo
    hgemm_nt<<<dim3(HID_ / 128, M / 256, 1), blk, HGEMM_SMEM>>>(
        ctxH, ctxL, WoH, WoL, bo, out, nullptr, nullptr,
        HH * DD, HH * DD, HH * DD, HID_, 1, 0, 0, 0, 0, 0, 0, 1.0f);
}

// round 10
// speedup vs baseline: 3.3099x; 1.5092x over previous
#include <cuda_runtime.h>
#include <cuda_bf16.h>
#include <math.h>
#include <stdint.h>

// Problem constants (Gemma attention, B=2,S=2048,HID=2048,H=8,KH=1,D=256)
#define BB   2
#define SS   2048
#define HID_ 2048
#define HH   8
#define DD   256
#define NQKV 2560   // packed Q(2048) + K(256) + V(256)

typedef __nv_bfloat16 bf16;
typedef __nv_bfloat162 bf162;
typedef long long ll;

// Panel geometry: A panels 256 rows x 32 k (hi 16K | lo 16K), B panels 128 rows.
#define PANA 32768
#define PANB 16384

// ---------------------------------------------------------------------------
// Scratch (__device__ globals — allocation-free)
// ---------------------------------------------------------------------------
__device__ float g_qkv[(size_t)BB * SS * NQKV];     // fp32 qkv proj
__device__ float g_bqkv[NQKV];

__device__ char g_hidpan [(size_t)16 * 64 * PANA];          // 33.5 MB
__device__ char g_wqkvpan[(size_t)20 * 64 * PANB];          // 21 MB
__device__ char g_wopan  [(size_t)16 * 64 * PANB];          // 16.8 MB
__device__ char g_qpan   [(size_t)BB * HH * 64 * PANA];     // 33.5 MB
__device__ char g_kpan   [(size_t)BB * 128 * PANB];         // 4.2 MB
__device__ char g_vtpan  [(size_t)BB * 128 * PANB];         // 4.2 MB
__device__ char g_attnpan[(size_t)BB * HH * 512 * PANA];    // 268 MB
__device__ char g_ctxpan [(size_t)16 * 64 * PANA];          // 33.5 MB

// ---------------------------------------------------------------------------
// PTX helpers
// ---------------------------------------------------------------------------
__device__ __forceinline__ uint32_t smem_u32(const void* p) {
    uint32_t a;
    asm("{ .reg .u64 t; cvta.to.shared.u64 t, %1; cvt.u32.u64 %0, t; }"
        : "=r"(a) : "l"(p));
    return a;
}

#define MBAR_INIT(addr, cnt) \
    asm volatile("mbarrier.init.shared.b64 [%0], %1;" :: "r"(addr), "r"(cnt) : "memory")

#define MBAR_ARRIVE(addr) \
    asm volatile("mbarrier.arrive.shared.b64 _, [%0];" :: "r"(addr) : "memory")

#define MBAR_EXPECT_TX(addr, bytes) \
    asm volatile("mbarrier.arrive.expect_tx.shared.b64 _, [%0], %1;" \
                 :: "r"(addr), "r"(bytes) : "memory")

#define WAITP(mbar_addr, parity) do {                                              \
    uint32_t _mbar = (uint32_t)(mbar_addr);                                        \
    uint32_t _par  = (uint32_t)(parity);                                           \
    uint32_t _done;                                                                \
    asm volatile(                                                                  \
        "{\n\t.reg .pred p;\n\t"                                                   \
        "mbarrier.try_wait.parity.acquire.cta.shared::cta.b64 p, [%1], %2;\n\t"    \
        "selp.b32 %0, 1, 0, p;\n\t}"                                               \
        : "=r"(_done) : "r"(_mbar), "r"(_par) : "memory");                         \
    if (!_done) {                                                                  \
        asm volatile(                                                              \
            "{\n\t.reg .pred P1;\n\t"                                              \
            "WAIT_LOOP_%=:\n\t"                                                    \
            "mbarrier.try_wait.parity.acquire.cta.shared::cta.b64 P1, [%0], %1, 0x989680;\n\t" \
            "@P1 bra.uni WAIT_DONE_%=;\n\t"                                        \
            "bra.uni WAIT_LOOP_%=;\n\t"                                            \
            "WAIT_DONE_%=:\n\t}"                                                   \
            :: "r"(_mbar), "r"(_par) : "memory");                                  \
    }                                                                              \
} while (0)

__device__ __forceinline__ void bulkcp(uint32_t dst, const void* src,
                                       uint32_t bytes, uint32_t mbar) {
    asm volatile(
        "cp.async.bulk.shared::cluster.global.mbarrier::complete_tx::bytes "
        "[%0], [%1], %2, [%3];"
        :: "r"(dst), "l"(src), "r"(bytes), "r"(mbar) : "memory");
}

__device__ __forceinline__ void ldm_x4(uint32_t* r, uint32_t addr) {
    asm volatile("ldmatrix.sync.aligned.m8n8.x4.shared.b16 {%0,%1,%2,%3}, [%4];"
                 : "=r"(r[0]), "=r"(r[1]), "=r"(r[2]), "=r"(r[3]) : "r"(addr));
}

__device__ __forceinline__ void mma_bf16(float* c, const uint32_t* a,
                                         uint32_t b0, uint32_t b1) {
    asm volatile(
        "mma.sync.aligned.m16n8k16.row.col.f32.bf16.bf16.f32 "
        "{%0,%1,%2,%3}, {%4,%5,%6,%7}, {%8,%9}, {%0,%1,%2,%3};"
        : "+f"(c[0]), "+f"(c[1]), "+f"(c[2]), "+f"(c[3])
        : "r"(a[0]), "r"(a[1]), "r"(a[2]), "r"(a[3]), "r"(b0), "r"(b1));
}

__device__ __forceinline__ void split1(float v, bf16& h, bf16& l) {
    h = __float2bfloat16(v);
    l = __float2bfloat16(v - __bfloat162float(h));
}

// SW64-swizzled byte offset of element (rin, cin) within a panel's hi region.
// 64B rows, 16B segments, seg ^= (row>>1)&3.
__device__ __forceinline__ uint32_t pan_off(int rin, int cin) {
    return (uint32_t)(rin * 64 + ((((cin >> 3) ^ ((rin >> 1) & 3))) << 4)
                      + ((cin & 7) << 1));
}

// ===========================================================================
// Panelized split-bf16 NT GEMM on HMMA (3-pass error-compensated)
//   CTA tile 256x128x32, 512 thr (16 warps, warp 64x32), 4-stage bulk-copy
//   pipeline with mbarriers. Operands are pre-packed panels.
// ===========================================================================
#define STG    (PANA + PANB)        // 49152
#define NST    4
#define GSMEM  (NST * STG)          // 196608

__global__ __launch_bounds__(512, 1)
void pgemm(const char* __restrict__ Apan, const char* __restrict__ Bpan,
           const float* __restrict__ bias, float* __restrict__ C,
           char* __restrict__ Cpan,
           int K, int ldc, int Hdim,
           ll sAb, ll sAh, ll sBb, ll sBh, ll sCb, ll sCh,
           float alpha)
{
    extern __shared__ __align__(128) char dsm[];
    __shared__ __align__(8) uint64_t mb[2 * NST];
    const uint32_t sbase = smem_u32(dsm);
    const uint32_t mbF = smem_u32(&mb[0]);
    const uint32_t mbE = smem_u32(&mb[NST]);

    const int tid  = threadIdx.x;
    const int wid  = tid >> 5;
    const int lane = tid & 31;
    const int wm   = wid >> 2;          // 0..3 (64-row band)
    const int wn   = wid & 3;           // 0..3 (32-col band)

    const int z  = blockIdx.z;
    const int bz = z / Hdim;
    const int hz = z - bz * Hdim;

    const int nc = K >> 5;
    const char* aSrc = Apan + (ll)bz * sAb + (ll)hz * sAh + (ll)blockIdx.y * nc * PANA;
    const char* bSrc = Bpan + (ll)bz * sBb + (ll)hz * sBh + (ll)blockIdx.x * nc * PANB;

    if (tid == 0) {
#pragma unroll
        for (int s = 0; s < NST; s++) {
            MBAR_INIT(mbF + 8 * s, 1);
            MBAR_INIT(mbE + 8 * s, 512);
        }
    }
    __syncthreads();

    auto produce = [&](int c) {
        if (c >= nc || tid != 0) return;
        const int s = c & 3, r = c >> 2;
        if (r > 0) WAITP(mbE + 8 * s, (r - 1) & 1);
        MBAR_EXPECT_TX(mbF + 8 * s, (uint32_t)STG);
        const uint32_t d = sbase + s * STG;
        bulkcp(d,        aSrc + (ll)c * PANA, PANA, mbF + 8 * s);
        bulkcp(d + PANA, bSrc + (ll)c * PANB, PANB, mbF + 8 * s);
    };

    float acc[4][4][4];
#pragma unroll
    for (int i = 0; i < 4; i++)
#pragma unroll
        for (int j = 0; j < 4; j++)
#pragma unroll
            for (int r = 0; r < 4; r++) acc[i][j][r] = 0.f;

    produce(0); produce(1); produce(2);

    const int rowloc = lane & 15;
    const int segb   = lane >> 4;
    const int xr     = (rowloc >> 1) & 3;

    for (int c = 0; c < nc; c++) {
        const int s = c & 3, r = c >> 2;
        produce(c + 3);
        WAITP(mbF + 8 * s, r & 1);

        const uint32_t tb  = sbase + s * STG;
        const uint32_t aH0 = tb + (wm * 64) * 64;
        const uint32_t aL0 = aH0 + 16384;
        const uint32_t bH0 = tb + PANA + (wn * 32) * 64;
        const uint32_t bL0 = bH0 + 8192;

#pragma unroll
        for (int k16 = 0; k16 < 2; k16++) {
            const uint32_t lo = (uint32_t)rowloc * 64
                              + (uint32_t)(((segb + 2 * k16) ^ xr) << 4);
            uint32_t bH[2][4], bL[2][4];
#pragma unroll
            for (int nt = 0; nt < 2; nt++) {
                ldm_x4(bH[nt], bH0 + nt * 1024 + lo);
                ldm_x4(bL[nt], bL0 + nt * 1024 + lo);
            }
#pragma unroll
            for (int mt = 0; mt < 4; mt++) {
                uint32_t aH[4], aL[4];
                ldm_x4(aH, aH0 + mt * 1024 + lo);
                ldm_x4(aL, aL0 + mt * 1024 + lo);
#pragma unroll
                for (int j = 0; j < 4; j++)
                    mma_bf16(acc[mt][j], aH, bH[j >> 1][j & 1], bH[j >> 1][2 + (j & 1)]);
#pragma unroll
                for (int j = 0; j < 4; j++)
                    mma_bf16(acc[mt][j], aL, bH[j >> 1][j & 1], bH[j >> 1][2 + (j & 1)]);
#pragma unroll
                for (int j = 0; j < 4; j++)
                    mma_bf16(acc[mt][j], aH, bL[j >> 1][j & 1], bL[j >> 1][2 + (j & 1)]);
            }
        }
        MBAR_ARRIVE(mbE + 8 * s);
    }

    // ---- epilogue ----
    float* Cb = nullptr;
    if (C) Cb = C + (ll)bz * sCb + (ll)hz * sCh
              + (ll)blockIdx.y * 256 * ldc + (ll)blockIdx.x * 128;
    const ll pb0 = Cpan ? ((ll)(bz * 8 + blockIdx.y) * 64 + hz * 8 + blockIdx.x * 4) : 0;
    const int colblk = blockIdx.x << 7;

#pragma unroll
    for (int mt = 0; mt < 4; mt++) {
        const int row0 = wm * 64 + mt * 16 + (lane >> 2);
#pragma unroll
        for (int hrow = 0; hrow < 2; hrow++) {
            const int row = row0 + hrow * 8;
#pragma unroll
            for (int j = 0; j < 4; j++) {
                const int col = wn * 32 + j * 8 + (lane & 3) * 2;
                float b0 = 0.f, b1 = 0.f;
                if (bias) { b0 = bias[colblk + col]; b1 = bias[colblk + col + 1]; }
                const float v0 = acc[mt][j][hrow * 2 + 0] * alpha + b0;
                const float v1 = acc[mt][j][hrow * 2 + 1] * alpha + b1;
                if (Cb) *(float2*)(Cb + (ll)row * ldc + col) = make_float2(v0, v1);
                if (Cpan) {
                    bf16 h0, l0, h1, l1;
                    split1(v0, h0, l0);
                    split1(v1, h1, l1);
                    char* p = Cpan + (pb0 + (col >> 5)) * (ll)PANA;
                    const uint32_t off = pan_off(row, col & 31);
                    *(bf162*)(p + off)         = __halves2bfloat162(h0, h1);
                    *(bf162*)(p + 16384 + off) = __halves2bfloat162(l0, l1);
                }
            }
        }
    }
}

// ---------------------------------------------------------------------------
// fp32 matrix (rows x C, row-major) -> split panels (tile rows T, hi|lo)
// ---------------------------------------------------------------------------
__global__ void split_panel(const float* __restrict__ x, char* __restrict__ pan,
                            int C, int T, int row0, ll n)
{
    ll i = ((ll)blockIdx.x * blockDim.x + threadIdx.x) * 4;
    if (i >= n) return;
    float4 v = *(const float4*)(x + i);
    const int row = (int)(i / C) + row0;
    const int col = (int)(i % C);
    const int it = row / T, rin = row % T;
    const int ic = col >> 5, cin = col & 31;
    char* p = pan + ((ll)it * (C >> 5) + ic) * (ll)(T * 128);
    const uint32_t off = pan_off(rin, cin);
    bf16 h0, l0, h1, l1, h2, l2, h3, l3;
    split1(v.x, h0, l0); split1(v.y, h1, l1);
    split1(v.z, h2, l2); split1(v.w, h3, l3);
    bf162 hi01 = __halves2bfloat162(h0, h1), hi23 = __halves2bfloat162(h2, h3);
    bf162 lo01 = __halves2bfloat162(l0, l1), lo23 = __halves2bfloat162(l2, l3);
    *(bf162*)(p + off)     = hi01;
    *(bf162*)(p + off + 4) = hi23;
    char* pl = p + (ll)T * 64;
    *(bf162*)(pl + off)     = lo01;
    *(bf162*)(pl + off + 4) = lo23;
}

// ---------------------------------------------------------------------------
// RoPE + panelize: one block (128 thr) per (bs, h) row of 256 elems.
// q: Hx=8, T=256 (A panels).  k: Hx=1, T=128 (B panels).
// ---------------------------------------------------------------------------
__global__ __launch_bounds__(128)
void rope_pan(const float* __restrict__ src, const int* __restrict__ pos,
              char* __restrict__ pan, int Hx, int T)
{
    const int blk = blockIdx.x;
    const int h   = blk % Hx;
    const int bs  = blk / Hx;
    const int b   = bs / SS, sI = bs % SS;
    const int t   = threadIdx.x;

    const float p   = (float)pos[bs];
    const float ivf = __expf(-(float)t * (9.210340371976184f / 128.f));
    float sn, cs;
    sincosf(p * ivf, &sn, &cs);
    const float* xr_ = src + (ll)bs * NQKV + h * DD;
    const float x1 = xr_[t], x2 = xr_[t + 128];
    const float y1 = cs * x1 - sn * x2;
    const float y2 = sn * x1 + cs * x2;

    const int it = sI / T, rin = sI % T;
    const int ntile = SS / T;
    const ll  g = ((ll)(b * Hx + h) * ntile + it) * 8;
    const ll  pbytes = (ll)T * 128;
    const ll  loskip = (ll)T * 64;

    bf16 hh, lv;
    {
        const int ic = t >> 5, cin = t & 31;
        char* pp = pan + (g + ic) * pbytes;
        const uint32_t off = pan_off(rin, cin);
        split1(y1, hh, lv);
        *(bf16*)(pp + off)          = hh;
        *(bf16*)(pp + loskip + off) = lv;
    }
    {
        const int d = t + 128;
        const int ic = d >> 5, cin = d & 31;
        char* pp = pan + (g + ic) * pbytes;
        const uint32_t off = pan_off(rin, cin);
        split1(y2, hh, lv);
        *(bf16*)(pp + off)          = hh;
        *(bf16*)(pp + loskip + off) = lv;
    }
}

// ---------------------------------------------------------------------------
// Transpose v (qkv col 2304) -> vT B-panels (per b: [ix in 2][ic in 64])
// ---------------------------------------------------------------------------
__global__ void transpose_pan(const float* __restrict__ qkv, char* __restrict__ pan)
{
    __shared__ float t[32][33];
    const int b  = blockIdx.z;
    const int s0 = blockIdx.x * 32;
    const int d0 = blockIdx.y * 32;
    const int tx = threadIdx.x, ty = threadIdx.y;
    const float* src = qkv + (ll)b * SS * NQKV + 2304;
#pragma unroll
    for (int i = 0; i < 32; i += 8)
        t[ty + i][tx] = src[(ll)(s0 + ty + i) * NQKV + d0 + tx];
    __syncthreads();
#pragma unroll
    for (int i = 0; i < 32; i += 8) {
        const int d  = d0 + ty + i;
        const int sI = s0 + tx;
        const int ix = d >> 7, rin = d & 127;
        const int ic = sI >> 5, cin = sI & 31;
        char* pp = pan + ((ll)(b * 2 + ix) * 64 + ic) * (ll)PANB;
        const uint32_t off = pan_off(rin, cin);
        bf16 h, l;
        split1(t[tx][ty + i], h, l);
        *(bf16*)(pp + off)        = h;
        *(bf16*)(pp + 8192 + off) = l;
    }
}

// ---------------------------------------------------------------------------
// Row softmax over attn (B,H,S,S) in place (+mask) + panelized split output
// ---------------------------------------------------------------------------
__global__ __launch_bounds__(256)
void softmax_pan(float* __restrict__ attn, const float* __restrict__ mask,
                 char* __restrict__ pan)
{
    const int HSrows = HH * SS;
    const ll r = blockIdx.x;
    const int b = (int)(r / HSrows);
    float* row = attn + r * (ll)SS;
    const float* mrow = mask + (ll)b * SS;

    const int tid  = threadIdx.x;
    const int w    = tid >> 5;
    const int lane = tid & 31;
    __shared__ float red[8];

    float v[8];
    float mx = -1e30f;
#pragma unroll
    for (int i = 0; i < 8; i++) {
        const int c = tid + i * 256;
        const float x = row[c] + mrow[c];
        v[i] = x;
        mx = fmaxf(mx, x);
    }
#pragma unroll
    for (int o = 16; o; o >>= 1) mx = fmaxf(mx, __shfl_xor_sync(0xffffffffu, mx, o));
    if (lane == 0) red[w] = mx;
    __syncthreads();
#pragma unroll
    for (int i = 0; i < 8; i++) mx = fmaxf(mx, red[i]);

    float s = 0.f;
#pragma unroll
    for (int i = 0; i < 8; i++) {
        v[i] = __expf(v[i] - mx);
        s += v[i];
    }
#pragma unroll
    for (int o = 16; o; o >>= 1) s += __shfl_xor_sync(0xffffffffu, s, o);
    __syncthreads();
    if (lane == 0) red[w] = s;
    __syncthreads();
    s = 0.f;
#pragma unroll
    for (int i = 0; i < 8; i++) s += red[i];
    const float inv = 1.f / s;

    const int n   = (int)(r % SS);
    const int rin = n & 255;
    const ll  gbase = (r / SS) * 512 + (ll)(n >> 8) * 64;
#pragma unroll
    for (int i = 0; i < 8; i++) {
        const int c = tid + i * 256;
        const float pv = v[i] * inv;
        row[c] = pv;
        const int ic = c >> 5, cin = c & 31;
        char* pp = pan + (gbase + ic) * (ll)PANA;
        const uint32_t off = pan_off(rin, cin);
        bf16 h, l;
        split1(pv, h, l);
        *(bf16*)(pp + off)         = h;
        *(bf16*)(pp + 16384 + off) = l;
    }
}

// ---------------------------------------------------------------------------
// Launch
// ---------------------------------------------------------------------------
extern "C" void kernel_launch(void* const* d_in, const int* in_sizes, int n_in,
                              void* d_out, int out_size)
{
    (void)in_sizes; (void)n_in; (void)out_size;

    const float* hidden = (const float*)d_in[0];
    const float* mask   = (const float*)d_in[1];
    const int*   pos    = (const int*)  d_in[2];
    const float* Wq     = (const float*)d_in[3];
    const float* bq     = (const float*)d_in[4];
    const float* Wk     = (const float*)d_in[5];
    const float* bk     = (const float*)d_in[6];
    const float* Wv     = (const float*)d_in[7];
    const float* bv     = (const float*)d_in[8];
    const float* Wo     = (const float*)d_in[9];
    const float* bo     = (const float*)d_in[10];

    float* out  = (float*)d_out;                      // (B,S,HID)
    float* attn = out + (size_t)BB * SS * HID_;       // (B,H,S,S)

    float *qkv, *bqkv;
    char *hidpan, *wqkvpan, *wopan, *qpan, *kpan, *vtpan, *attnpan, *ctxpan;
    cudaGetSymbolAddress((void**)&qkv,     g_qkv);
    cudaGetSymbolAddress((void**)&bqkv,    g_bqkv);
    cudaGetSymbolAddress((void**)&hidpan,  g_hidpan);
    cudaGetSymbolAddress((void**)&wqkvpan, g_wqkvpan);
    cudaGetSymbolAddress((void**)&wopan,   g_wopan);
    cudaGetSymbolAddress((void**)&qpan,    g_qpan);
    cudaGetSymbolAddress((void**)&kpan,    g_kpan);
    cudaGetSymbolAddress((void**)&vtpan,   g_vtpan);
    cudaGetSymbolAddress((void**)&attnpan, g_attnpan);
    cudaGetSymbolAddress((void**)&ctxpan,  g_ctxpan);

    cudaFuncSetAttribute(pgemm, cudaFuncAttributeMaxDynamicSharedMemorySize, GSMEM);

    const int M = BB * SS;   // 4096
    dim3 blk(256);
    dim3 gblk(512);

    // 0) panelize inputs
    {
        ll n = (ll)BB * SS * HID_;
        split_panel<<<(unsigned)((n / 4 + 255) / 256), blk>>>(hidden, hidpan,
                                                              HID_, 256, 0, n);
        n = (ll)HID_ * HID_;
        split_panel<<<(unsigned)((n / 4 + 255) / 256), blk>>>(Wq, wqkvpan,
                                                              HID_, 128, 0, n);
        n = (ll)DD * HID_;
        split_panel<<<(unsigned)((n / 4 + 255) / 256), blk>>>(Wk, wqkvpan,
                                                              HID_, 128, 2048, n);
        split_panel<<<(unsigned)((n / 4 + 255) / 256), blk>>>(Wv, wqkvpan,
                                                              HID_, 128, 2304, n);
        n = (ll)HID_ * HH * DD;
        split_panel<<<(unsigned)((n / 4 + 255) / 256), blk>>>(Wo, wopan,
                                                              HID_, 128, 0, n);
        cudaMemcpyAsync(bqkv,        bq, 2048 * sizeof(float), cudaMemcpyDeviceToDevice);
        cudaMemcpyAsync(bqkv + 2048, bk,  256 * sizeof(float), cudaMemcpyDeviceToDevice);
        cudaMemcpyAsync(bqkv + 2304, bv,  256 * sizeof(float), cudaMemcpyDeviceToDevice);
    }

    // 1) fused QKV projection: qkv = hidden @ Wqkv^T + bqkv  (4096 x 2560 x 2048)
    pgemm<<<dim3(NQKV / 128, M / 256, 1), gblk, GSMEM>>>(
        hidpan, wqkvpan, bqkv, qkv, nullptr,
        HID_, NQKV, 1, 0, 0, 0, 0, 0, 0, 1.0f);

    // 2) RoPE + panelize q (A panels) and k (B panels)
    rope_pan<<<BB * SS * HH, 128>>>(qkv,        pos, qpan, HH, 256);
    rope_pan<<<BB * SS,      128>>>(qkv + 2048, pos, kpan, 1,  128);

    // 3) vT B-panels
    transpose_pan<<<dim3(SS / 32, DD / 32, BB), dim3(32, 8)>>>(qkv, vtpan);

    // 4) scores = (q @ k^T)/16 -> attn fp32 region   (per bh: 2048x2048x256)
    pgemm<<<dim3(SS / 128, SS / 256, BB * HH), gblk, GSMEM>>>(
        qpan, kpan, nullptr, attn, nullptr,
        DD, SS, HH,
        (ll)HH * 64 * PANA, (ll)64 * PANA,
        (ll)128 * PANB, 0,
        (ll)HH * SS * SS, (ll)SS * SS,
        0.0625f);

    // 5) softmax in place (+mask) + panelized attn split
    softmax_pan<<<BB * HH * SS, blk>>>(attn, mask, attnpan);

    // 6) ctx = attn @ v  -> ctx panels (per bh: 2048x256x2048)
    pgemm<<<dim3(DD / 128, SS / 256, BB * HH), gblk, GSMEM>>>(
        attnpan, vtpan, nullptr, nullptr, ctxpan,
        SS, 0, HH,
        (ll)HH * 512 * PANA, (ll)512 * PANA,
        (ll)128 * PANB, 0,
        0, 0,
        1.0f);

    // 7) out = ctx @ Wo^T + bo   (4096 x 2048 x 2048)
    pgemm<<<dim3(HID_ / 128, M / 256, 1), gblk, GSMEM>>>(
        ctxpan, wopan, bo, out, nullptr,
        HH * DD, HID_, 1, 0, 0, 0, 0, 0, 0, 1.0f);
}